// round 5
// baseline (speedup 1.0000x reference)
#include <cuda_runtime.h>
#include <cuda_bf16.h>
#include <math.h>
#include <stdint.h>

#define BB 4096
#define HH 1024
#define NG 5120
#define BH (4096*1024)

// GEMM tiling: CTA 256x128, 8 warps (4x2), warp 64x64, K-step 32, 3-stage cp.async
#define TM 256
#define TN 128
#define RS 40                          // padded row stride (bf16) = 80B
#define A_ARR 20480                    // 256*RS*2
#define W_ARR 10240                    // 128*RS*2
#define STG_BYTES 61440                // 2*A_ARR + 2*W_ARR
#define NSTAGE 3
#define SMEM_BYTES (NSTAGE*STG_BYTES)  // 184320

// ---------------- scratch (device globals; no allocs) ----------------
__device__ __nv_bfloat16 s_x_hi[(size_t)BB*HH],  s_x_lo[(size_t)BB*HH];
__device__ __nv_bfloat16 s_h_hi[(size_t)BB*HH],  s_h_lo[(size_t)BB*HH];
__device__ __nv_bfloat16 s_sg_hi[(size_t)BB*HH], s_sg_lo[(size_t)BB*HH];
__device__ __nv_bfloat16 s_r1_hi[(size_t)BB*HH], s_r1_lo[(size_t)BB*HH];
__device__ __nv_bfloat16 s_r2_hi[(size_t)BB*HH], s_r2_lo[(size_t)BB*HH];
__device__ __nv_bfloat16 w_Wx_hi[(size_t)NG*HH], w_Wx_lo[(size_t)NG*HH];
__device__ __nv_bfloat16 w_Ux_hi[(size_t)NG*HH], w_Ux_lo[(size_t)NG*HH];
__device__ __nv_bfloat16 w_a1_hi[(size_t)HH*2048], w_a1_lo[(size_t)HH*2048];
__device__ __nv_bfloat16 w_sw_hi[(size_t)HH*HH], w_sw_lo[(size_t)HH*HH];
__device__ __nv_bfloat16 w_r1_hi[(size_t)HH*HH], w_r1_lo[(size_t)HH*HH];
__device__ __nv_bfloat16 w_r2_hi[(size_t)HH*HH], w_r2_lo[(size_t)HH*HH];
__device__ __nv_bfloat16 w_r3_hi[(size_t)HH*HH], w_r3_lo[(size_t)HH*HH];
__device__ float g_gates[(size_t)BB*NG];
__device__ float g_ah[(size_t)BB*HH];
__device__ float g_alpha[BB];

// ---------------- helpers ----------------
__device__ __forceinline__ uint32_t smem_u32(const void* p) {
    uint32_t a;
    asm("{ .reg .u64 t; cvta.to.shared.u64 t, %1; cvt.u32.u64 %0, t; }" : "=r"(a) : "l"(p));
    return a;
}
__device__ __forceinline__ void ldsm4(uint32_t& r0, uint32_t& r1, uint32_t& r2, uint32_t& r3, uint32_t a) {
    asm volatile("ldmatrix.sync.aligned.m8n8.x4.shared.b16 {%0,%1,%2,%3}, [%4];"
        : "=r"(r0), "=r"(r1), "=r"(r2), "=r"(r3) : "r"(a));
}
__device__ __forceinline__ void mma16816(float* c, const uint32_t* a, const uint32_t* b) {
    asm volatile("mma.sync.aligned.m16n8k16.row.col.f32.bf16.bf16.f32 "
        "{%0,%1,%2,%3}, {%4,%5,%6,%7}, {%8,%9}, {%0,%1,%2,%3};"
        : "+f"(c[0]), "+f"(c[1]), "+f"(c[2]), "+f"(c[3])
        : "r"(a[0]), "r"(a[1]), "r"(a[2]), "r"(a[3]), "r"(b[0]), "r"(b[1]));
}
#define CP_ASYNC16(dst, src) \
    asm volatile("cp.async.cg.shared.global [%0], [%1], 16;" :: "r"(dst), "l"(src))
#define CP_COMMIT()  asm volatile("cp.async.commit_group;" ::: "memory")
#define CP_WAIT(n)   asm volatile("cp.async.wait_group %0;" :: "n"(n) : "memory")

__device__ __forceinline__ void split2(float v0, float v1, __nv_bfloat162& hi, __nv_bfloat162& lo) {
    __nv_bfloat16 h0 = __float2bfloat16_rn(v0), h1 = __float2bfloat16_rn(v1);
    __nv_bfloat16 l0 = __float2bfloat16_rn(v0 - __bfloat162float(h0));
    __nv_bfloat16 l1 = __float2bfloat16_rn(v1 - __bfloat162float(h1));
    hi = __nv_bfloat162(h0, h1); lo = __nv_bfloat162(l0, l1);
}

// ---------------- fused conversion kernels ----------------
// activations: x, h, (ssg+h) in one pass
__global__ void __launch_bounds__(256)
cvt_act(const float4* __restrict__ x, const float4* __restrict__ h, const float4* __restrict__ ssg,
        __nv_bfloat162* __restrict__ xh, __nv_bfloat162* __restrict__ xl,
        __nv_bfloat162* __restrict__ hh, __nv_bfloat162* __restrict__ hl,
        __nv_bfloat162* __restrict__ sgh, __nv_bfloat162* __restrict__ sgl)
{
    int i = blockIdx.x * 256 + threadIdx.x;         // BH/4 chunks
    float4 vx = x[i], vh = h[i], vs = ssg[i];
    __nv_bfloat162 a, b;
    split2(vx.x, vx.y, a, b); xh[2*i] = a;  xl[2*i] = b;
    split2(vx.z, vx.w, a, b); xh[2*i+1] = a; xl[2*i+1] = b;
    split2(vh.x, vh.y, a, b); hh[2*i] = a;  hl[2*i] = b;
    split2(vh.z, vh.w, a, b); hh[2*i+1] = a; hl[2*i+1] = b;
    split2(vs.x + vh.x, vs.y + vh.y, a, b); sgh[2*i] = a;  sgl[2*i] = b;
    split2(vs.z + vh.z, vs.w + vh.w, a, b); sgh[2*i+1] = a; sgl[2*i+1] = b;
}
// all 7 weight tensors in one grid
#define CW1 1310720            // Wx chunks (5120*1024/4)
#define CW2 2621440            // +Ux
#define CW3 3145728            // +a1 (1024*2048/4)
#define CWS 262144             // each H*H/4
__global__ void __launch_bounds__(256)
cvt_w_all(const float4* __restrict__ Wx, const float4* __restrict__ Ux, const float4* __restrict__ a1,
          const float4* __restrict__ sw, const float4* __restrict__ r1,
          const float4* __restrict__ r2, const float4* __restrict__ r3,
          __nv_bfloat162* __restrict__ Wxh, __nv_bfloat162* __restrict__ Wxl,
          __nv_bfloat162* __restrict__ Uxh, __nv_bfloat162* __restrict__ Uxl,
          __nv_bfloat162* __restrict__ a1h, __nv_bfloat162* __restrict__ a1l,
          __nv_bfloat162* __restrict__ swh, __nv_bfloat162* __restrict__ swl,
          __nv_bfloat162* __restrict__ w1h, __nv_bfloat162* __restrict__ w1l,
          __nv_bfloat162* __restrict__ w2h, __nv_bfloat162* __restrict__ w2l,
          __nv_bfloat162* __restrict__ w3h, __nv_bfloat162* __restrict__ w3l)
{
    int i = blockIdx.x * 256 + threadIdx.x;
    const float4* src; __nv_bfloat162 *oh, *ol; int j;
    if      (i < CW1)          { src = Wx; oh = Wxh; ol = Wxl; j = i; }
    else if (i < CW2)          { src = Ux; oh = Uxh; ol = Uxl; j = i - CW1; }
    else if (i < CW3)          { src = a1; oh = a1h; ol = a1l; j = i - CW2; }
    else if (i < CW3 + CWS)    { src = sw; oh = swh; ol = swl; j = i - CW3; }
    else if (i < CW3 + 2*CWS)  { src = r1; oh = w1h; ol = w1l; j = i - CW3 - CWS; }
    else if (i < CW3 + 3*CWS)  { src = r2; oh = w2h; ol = w2l; j = i - CW3 - 2*CWS; }
    else                       { src = r3; oh = w3h; ol = w3l; j = i - CW3 - 3*CWS; }
    float4 v = src[j];
    __nv_bfloat162 a, b;
    split2(v.x, v.y, a, b); oh[2*j] = a;   ol[2*j] = b;
    split2(v.z, v.w, a, b); oh[2*j+1] = a; ol[2*j+1] = b;
}

// ---------------- bf16-split mma.sync GEMM (256x128 CTA, 3-stage) ----------------
// C[M,N] = epi( A1@W1^T [+ A2@W2^T] + b1 [+ b2] )
// MODE: 0 fp32 out ; 1 relu fp32 ; 2 gate acts ; 3 r3+cell fused ; 4 relu + bf16 pair out
template<int MODE>
__global__ void __launch_bounds__(256, 1)
mma_gemm(const __nv_bfloat16* __restrict__ A1h, const __nv_bfloat16* __restrict__ A1l, int lda1,
         const __nv_bfloat16* __restrict__ W1h, const __nv_bfloat16* __restrict__ W1l, int ldw1, int s1,
         const __nv_bfloat16* __restrict__ A2h, const __nv_bfloat16* __restrict__ A2l, int lda2,
         const __nv_bfloat16* __restrict__ W2h, const __nv_bfloat16* __restrict__ W2l, int ldw2, int s2,
         const float* __restrict__ b1, const float* __restrict__ b2,
         float* __restrict__ Cf, __nv_bfloat16* __restrict__ Chi, __nv_bfloat16* __restrict__ Clo,
         int ldc,
         const float* __restrict__ gates, const float* __restrict__ c_prev,
         const float* __restrict__ alphav, const float* __restrict__ ssg,
         float* __restrict__ out_h, float* __restrict__ out_c)
{
    extern __shared__ char smem[];
    const uint32_t sbase = smem_u32(smem);
    const int tid = threadIdx.x, wid = tid >> 5, lane = tid & 31;
    const int wm = wid >> 1, wn = wid & 1;        // 4 x 2 warp grid, warp 64x64
    const int m0 = blockIdx.y * TM, n0 = blockIdx.x * TN;
    const int S = s1 + s2;

    float acc[4][8][4];
#pragma unroll
    for (int a = 0; a < 4; ++a)
#pragma unroll
        for (int b = 0; b < 8; ++b)
#pragma unroll
            for (int q = 0; q < 4; ++q) acc[a][b][q] = 0.f;

    auto issue_load = [&](int s) {
        const __nv_bfloat16 *Ah, *Al, *Wh, *Wl; int lda, ldw, koff;
        if (s < s1) { Ah = A1h; Al = A1l; Wh = W1h; Wl = W1l; lda = lda1; ldw = ldw1; koff = s * 32; }
        else        { Ah = A2h; Al = A2l; Wh = W2h; Wl = W2l; lda = lda2; ldw = ldw2; koff = (s - s1) * 32; }
        uint32_t dst0 = sbase + (uint32_t)(s % NSTAGE) * STG_BYTES;
#pragma unroll
        for (int i = 0; i < 12; ++i) {
            int c = tid + i * 256;
            uint32_t d; const __nv_bfloat16* g;
            if (i < 8) {                      // A hi/lo: 2048 chunks
                int arr = c >> 10, r = (c & 1023) >> 2, q = c & 3;
                d = dst0 + arr * A_ARR + r * 80 + q * 16;
                g = (arr ? Al : Ah) + (size_t)(m0 + r) * lda + koff + q * 8;
            } else {                          // W hi/lo: 1024 chunks
                int c2 = c - 2048;
                int arr = c2 >> 9, r = (c2 & 511) >> 2, q = c2 & 3;
                d = dst0 + 2 * A_ARR + arr * W_ARR + r * 80 + q * 16;
                g = (arr ? Wl : Wh) + (size_t)(n0 + r) * ldw + koff + q * 8;
            }
            CP_ASYNC16(d, g);
        }
        CP_COMMIT();
    };

    issue_load(0);
    issue_load(1);

    for (int s = 0; s < S; ++s) {
        if (s + 1 < S) CP_WAIT(1); else CP_WAIT(0);
        __syncthreads();
        if (s + 2 < S) issue_load(s + 2);

        uint32_t SB = sbase + (uint32_t)(s % NSTAGE) * STG_BYTES;
        uint32_t Ahb = SB, Alb = SB + A_ARR;
        uint32_t Whb = SB + 2 * A_ARR, Wlb = SB + 2 * A_ARR + W_ARR;

#pragma unroll
        for (int k16 = 0; k16 < 2; ++k16) {
            const int k0 = k16 * 16;
            uint32_t bh[8][2], bl[8][2];
            {
                const int g = lane >> 3;
                const int rb = wn * 64 + ((g >> 1) << 3) + (lane & 7);
                const int cb = k0 + ((g & 1) << 3);
#pragma unroll
                for (int p = 0; p < 4; ++p) {       // pair p covers nb=2p, 2p+1
                    uint32_t off = (uint32_t)((rb + p * 16) * RS + cb) * 2;
                    ldsm4(bh[2*p][0], bh[2*p][1], bh[2*p+1][0], bh[2*p+1][1], Whb + off);
                    ldsm4(bl[2*p][0], bl[2*p][1], bl[2*p+1][0], bl[2*p+1][1], Wlb + off);
                }
            }
            const int ra = wm * 64 + (lane & 15);
            const int ca = k0 + ((lane >> 4) << 3);
#pragma unroll
            for (int mb = 0; mb < 4; ++mb) {
                uint32_t ah[4], al[4];
                uint32_t off = (uint32_t)((ra + mb * 16) * RS + ca) * 2;
                ldsm4(ah[0], ah[1], ah[2], ah[3], Ahb + off);
                ldsm4(al[0], al[1], al[2], al[3], Alb + off);
                // split-major ordering: dependency distance 8
#pragma unroll
                for (int nb = 0; nb < 8; ++nb) mma16816(acc[mb][nb], ah, bh[nb]);
#pragma unroll
                for (int nb = 0; nb < 8; ++nb) mma16816(acc[mb][nb], ah, bl[nb]);
#pragma unroll
                for (int nb = 0; nb < 8; ++nb) mma16816(acc[mb][nb], al, bh[nb]);
            }
        }
        __syncthreads();
    }

    // ---------------- epilogue ----------------
#pragma unroll
    for (int mb = 0; mb < 4; ++mb) {
#pragma unroll
        for (int nb = 0; nb < 8; ++nb) {
#pragma unroll
            for (int h = 0; h < 2; ++h) {
                const int m = m0 + wm * 64 + mb * 16 + (lane >> 2) + h * 8;
                const int n = n0 + wn * 64 + nb * 8 + 2 * (lane & 3);
                float v0 = acc[mb][nb][2 * h]     + b1[n];
                float v1 = acc[mb][nb][2 * h + 1] + b1[n + 1];
                if (b2) { v0 += b2[n]; v1 += b2[n + 1]; }
                if (MODE == 1 || MODE == 4) { v0 = fmaxf(v0, 0.f); v1 = fmaxf(v1, 0.f); }
                if (MODE == 2) {
                    const int g = n >> 10;       // both cols same gate (n even)
                    if (g == 3) { v0 = tanhf(v0); v1 = tanhf(v1); }
                    else { v0 = 1.f / (1.f + __expf(-v0)); v1 = 1.f / (1.f + __expf(-v1)); }
                }
                const size_t gm = (size_t)m * ldc + n;
                if (MODE == 4) {
                    __nv_bfloat162 hi2, lo2;
                    split2(v0, v1, hi2, lo2);
                    *(__nv_bfloat162*)(Chi + gm) = hi2;
                    *(__nv_bfloat162*)(Clo + gm) = lo2;
                } else if (MODE == 3) {
                    // v = residual; fused LSTM cell update
                    const size_t gb = (size_t)m * NG + n;
                    const float a = alphav[m];
                    float2 cp = *(const float2*)(c_prev + gm);
                    float2 sg = *(const float2*)(ssg + gm);
                    float c0 = gates[gb + 1024] * cp.x
                             + gates[gb] * gates[gb + 3072] * gates[gb + 4096] * a * sg.x + v0;
                    float c1 = gates[gb + 1025] * cp.y
                             + gates[gb + 1] * gates[gb + 3073] * gates[gb + 4097] * a * sg.y + v1;
                    float2 oc; oc.x = c0; oc.y = c1;
                    float2 oh; oh.x = gates[gb + 2048] * tanhf(c0);
                    oh.y = gates[gb + 2049] * tanhf(c1);
                    *(float2*)(out_c + gm) = oc;
                    *(float2*)(out_h + gm) = oh;
                } else {
                    float2 o; o.x = v0; o.y = v1;
                    *(float2*)(Cf + gm) = o;
                }
            }
        }
    }
}

// ---------------- alpha: sigmoid(ah @ a2_w^T + a2_b) ----------------
__global__ void __launch_bounds__(256)
alpha_kernel(const float* __restrict__ ah, const float* __restrict__ a2w,
             const float* __restrict__ a2b, float* __restrict__ alpha)
{
    const int m = blockIdx.x;
    const int t = threadIdx.x;
    float s = 0.f;
#pragma unroll
    for (int k = t; k < 1024; k += 256)
        s += ah[(size_t)m * 1024 + k] * a2w[k];
    for (int o = 16; o; o >>= 1) s += __shfl_down_sync(0xffffffffu, s, o);
    __shared__ float red[8];
    if ((t & 31) == 0) red[t >> 5] = s;
    __syncthreads();
    if (t == 0) {
        float tot = 0.f;
#pragma unroll
        for (int i = 0; i < 8; ++i) tot += red[i];
        alpha[m] = 1.f / (1.f + __expf(-(tot + a2b[0])));
    }
}

// ---------------- launch ----------------
extern "C" void kernel_launch(void* const* d_in, const int* in_sizes, int n_in,
                              void* d_out, int out_size)
{
    const float* x      = (const float*)d_in[0];
    const float* h_prev = (const float*)d_in[1];
    const float* c_prev = (const float*)d_in[2];
    const float* ssg_st = (const float*)d_in[3];
    const float* Wx     = (const float*)d_in[4];
    const float* bWx    = (const float*)d_in[5];
    const float* Ux     = (const float*)d_in[6];
    const float* bUx    = (const float*)d_in[7];
    const float* a1_w   = (const float*)d_in[8];
    const float* a1_b   = (const float*)d_in[9];
    const float* a2_w   = (const float*)d_in[10];
    const float* a2_b   = (const float*)d_in[11];
    const float* r1_w   = (const float*)d_in[12];
    const float* r1_b   = (const float*)d_in[13];
    const float* r2_w   = (const float*)d_in[14];
    const float* r2_b   = (const float*)d_in[15];
    const float* r3_w   = (const float*)d_in[16];
    const float* r3_b   = (const float*)d_in[17];
    const float* ssg_w  = (const float*)d_in[18];
    const float* ssg_b  = (const float*)d_in[19];

    float* out = (float*)d_out;
    float* out_h   = out;
    float* out_c   = out + (size_t)BH;
    float* out_ssg = out + 2 * (size_t)BH;

    __nv_bfloat16 *xh, *xl, *hh, *hl, *sgh, *sgl, *r1h, *r1l, *r2h, *r2l;
    __nv_bfloat16 *Wxh, *Wxl, *Uxh, *Uxl, *a1h, *a1l, *swh, *swl, *w1h, *w1l, *w2h, *w2l, *w3h, *w3l;
    float *gates, *ah, *alpha;
    cudaGetSymbolAddress((void**)&xh, s_x_hi);   cudaGetSymbolAddress((void**)&xl, s_x_lo);
    cudaGetSymbolAddress((void**)&hh, s_h_hi);   cudaGetSymbolAddress((void**)&hl, s_h_lo);
    cudaGetSymbolAddress((void**)&sgh, s_sg_hi); cudaGetSymbolAddress((void**)&sgl, s_sg_lo);
    cudaGetSymbolAddress((void**)&r1h, s_r1_hi); cudaGetSymbolAddress((void**)&r1l, s_r1_lo);
    cudaGetSymbolAddress((void**)&r2h, s_r2_hi); cudaGetSymbolAddress((void**)&r2l, s_r2_lo);
    cudaGetSymbolAddress((void**)&Wxh, w_Wx_hi); cudaGetSymbolAddress((void**)&Wxl, w_Wx_lo);
    cudaGetSymbolAddress((void**)&Uxh, w_Ux_hi); cudaGetSymbolAddress((void**)&Uxl, w_Ux_lo);
    cudaGetSymbolAddress((void**)&a1h, w_a1_hi); cudaGetSymbolAddress((void**)&a1l, w_a1_lo);
    cudaGetSymbolAddress((void**)&swh, w_sw_hi); cudaGetSymbolAddress((void**)&swl, w_sw_lo);
    cudaGetSymbolAddress((void**)&w1h, w_r1_hi); cudaGetSymbolAddress((void**)&w1l, w_r1_lo);
    cudaGetSymbolAddress((void**)&w2h, w_r2_hi); cudaGetSymbolAddress((void**)&w2l, w_r2_lo);
    cudaGetSymbolAddress((void**)&w3h, w_r3_hi); cudaGetSymbolAddress((void**)&w3l, w_r3_lo);
    cudaGetSymbolAddress((void**)&gates, g_gates);
    cudaGetSymbolAddress((void**)&ah, g_ah);
    cudaGetSymbolAddress((void**)&alpha, g_alpha);

    cudaFuncSetAttribute(mma_gemm<0>, cudaFuncAttributeMaxDynamicSharedMemorySize, SMEM_BYTES);
    cudaFuncSetAttribute(mma_gemm<1>, cudaFuncAttributeMaxDynamicSharedMemorySize, SMEM_BYTES);
    cudaFuncSetAttribute(mma_gemm<2>, cudaFuncAttributeMaxDynamicSharedMemorySize, SMEM_BYTES);
    cudaFuncSetAttribute(mma_gemm<3>, cudaFuncAttributeMaxDynamicSharedMemorySize, SMEM_BYTES);
    cudaFuncSetAttribute(mma_gemm<4>, cudaFuncAttributeMaxDynamicSharedMemorySize, SMEM_BYTES);

    const dim3 blk(256);

    // fused conversions (2 launches)
    cvt_act<<<BH / 4 / 256, blk>>>((const float4*)x, (const float4*)h_prev, (const float4*)ssg_st,
                                   (__nv_bfloat162*)xh, (__nv_bfloat162*)xl,
                                   (__nv_bfloat162*)hh, (__nv_bfloat162*)hl,
                                   (__nv_bfloat162*)sgh, (__nv_bfloat162*)sgl);
    cvt_w_all<<<(CW3 + 4*CWS) / 256, blk>>>((const float4*)Wx, (const float4*)Ux, (const float4*)a1_w,
                                            (const float4*)ssg_w, (const float4*)r1_w,
                                            (const float4*)r2_w, (const float4*)r3_w,
                                            (__nv_bfloat162*)Wxh, (__nv_bfloat162*)Wxl,
                                            (__nv_bfloat162*)Uxh, (__nv_bfloat162*)Uxl,
                                            (__nv_bfloat162*)a1h, (__nv_bfloat162*)a1l,
                                            (__nv_bfloat162*)swh, (__nv_bfloat162*)swl,
                                            (__nv_bfloat162*)w1h, (__nv_bfloat162*)w1l,
                                            (__nv_bfloat162*)w2h, (__nv_bfloat162*)w2l,
                                            (__nv_bfloat162*)w3h, (__nv_bfloat162*)w3l);

    const dim3 grid_g(NG / TN, BB / TM);   // 40 x 16
    const dim3 grid_h(HH / TN, BB / TM);   // 8 x 16

    // gates = act( x@Wx^T + h@Ux^T + biases )
    mma_gemm<2><<<grid_g, blk, SMEM_BYTES>>>(xh, xl, 1024, Wxh, Wxl, 1024, 32,
                                             hh, hl, 1024, Uxh, Uxl, 1024, 32,
                                             bWx, bUx, gates, nullptr, nullptr, NG,
                                             nullptr, nullptr, nullptr, nullptr, nullptr, nullptr);
    // alpha hidden = relu( x@a1[:, :1024]^T + h@a1[:, 1024:]^T + a1_b )
    mma_gemm<1><<<grid_h, blk, SMEM_BYTES>>>(xh, xl, 1024, a1h, a1l, 2048, 32,
                                             hh, hl, 1024, a1h + 1024, a1l + 1024, 2048, 32,
                                             a1_b, nullptr, ah, nullptr, nullptr, HH,
                                             nullptr, nullptr, nullptr, nullptr, nullptr, nullptr);
    alpha_kernel<<<BB, blk>>>(ah, a2_w, a2_b, alpha);
    // ssg_new = (ssg+h)@ssg_w^T + ssg_b
    mma_gemm<0><<<grid_h, blk, SMEM_BYTES>>>(sgh, sgl, 1024, swh, swl, 1024, 32,
                                             nullptr, nullptr, 0, nullptr, nullptr, 0, 0,
                                             ssg_b, nullptr, out_ssg, nullptr, nullptr, HH,
                                             nullptr, nullptr, nullptr, nullptr, nullptr, nullptr);
    // r1 = relu(h@r1_w^T + b) -> bf16 pair
    mma_gemm<4><<<grid_h, blk, SMEM_BYTES>>>(hh, hl, 1024, w1h, w1l, 1024, 32,
                                             nullptr, nullptr, 0, nullptr, nullptr, 0, 0,
                                             r1_b, nullptr, nullptr, r1h, r1l, HH,
                                             nullptr, nullptr, nullptr, nullptr, nullptr, nullptr);
    // r2 = relu(r1@r2_w^T + b) -> bf16 pair
    mma_gemm<4><<<grid_h, blk, SMEM_BYTES>>>(r1h, r1l, 1024, w2h, w2l, 1024, 32,
                                             nullptr, nullptr, 0, nullptr, nullptr, 0, 0,
                                             r2_b, nullptr, nullptr, r2h, r2l, HH,
                                             nullptr, nullptr, nullptr, nullptr, nullptr, nullptr);
    // residual GEMM + fused LSTM cell -> out_h, out_c
    mma_gemm<3><<<grid_h, blk, SMEM_BYTES>>>(r2h, r2l, 1024, w3h, w3l, 1024, 32,
                                             nullptr, nullptr, 0, nullptr, nullptr, 0, 0,
                                             r3_b, nullptr, nullptr, nullptr, nullptr, HH,
                                             gates, c_prev, alpha, out_ssg, out_h, out_c);
}

// round 6
// speedup vs baseline: 1.1597x; 1.1597x over previous
#include <cuda_runtime.h>
#include <cuda_bf16.h>
#include <math.h>
#include <stdint.h>

#define BB 4096
#define HH 1024
#define NG 5120
#define BH (4096*1024)

// GEMM tiling: CTA 128x128, 8 warps (2x4), warp 64x32, K-step 32, 2-stage, 2 CTAs/SM
#define RS 40                        // padded smem row stride (bf16) = 80B
#define ARR_BYTES (128*RS*2)         // 10240 per tile array
#define STG_BYTES (4*ARR_BYTES)      // 40960 per stage (Ah,Al,Wh,Wl)
#define SMEM_BYTES (2*STG_BYTES)     // 81920 double-buffered

// ---------------- scratch (device globals; no allocs) ----------------
__device__ __nv_bfloat16 s_x_hi[(size_t)BB*HH],  s_x_lo[(size_t)BB*HH];
__device__ __nv_bfloat16 s_h_hi[(size_t)BB*HH],  s_h_lo[(size_t)BB*HH];
__device__ __nv_bfloat16 s_sg_hi[(size_t)BB*HH], s_sg_lo[(size_t)BB*HH];
__device__ __nv_bfloat16 s_r1_hi[(size_t)BB*HH], s_r1_lo[(size_t)BB*HH];
__device__ __nv_bfloat16 s_r2_hi[(size_t)BB*HH], s_r2_lo[(size_t)BB*HH];
__device__ __nv_bfloat16 w_Wx_hi[(size_t)NG*HH], w_Wx_lo[(size_t)NG*HH];
__device__ __nv_bfloat16 w_Ux_hi[(size_t)NG*HH], w_Ux_lo[(size_t)NG*HH];
__device__ __nv_bfloat16 w_a1_hi[(size_t)HH*2048], w_a1_lo[(size_t)HH*2048];
__device__ __nv_bfloat16 w_sw_hi[(size_t)HH*HH], w_sw_lo[(size_t)HH*HH];
__device__ __nv_bfloat16 w_r1_hi[(size_t)HH*HH], w_r1_lo[(size_t)HH*HH];
__device__ __nv_bfloat16 w_r2_hi[(size_t)HH*HH], w_r2_lo[(size_t)HH*HH];
__device__ __nv_bfloat16 w_r3_hi[(size_t)HH*HH], w_r3_lo[(size_t)HH*HH];
__device__ float g_gates[(size_t)BB*NG];
__device__ float g_ah[(size_t)BB*HH];
__device__ float g_alpha[BB];

// ---------------- helpers ----------------
__device__ __forceinline__ uint32_t smem_u32(const void* p) {
    uint32_t a;
    asm("{ .reg .u64 t; cvta.to.shared.u64 t, %1; cvt.u32.u64 %0, t; }" : "=r"(a) : "l"(p));
    return a;
}
__device__ __forceinline__ void ldsm4(uint32_t& r0, uint32_t& r1, uint32_t& r2, uint32_t& r3, uint32_t a) {
    asm volatile("ldmatrix.sync.aligned.m8n8.x4.shared.b16 {%0,%1,%2,%3}, [%4];"
        : "=r"(r0), "=r"(r1), "=r"(r2), "=r"(r3) : "r"(a));
}
__device__ __forceinline__ void mma16816(float* c, const uint32_t* a, const uint32_t* b) {
    asm volatile("mma.sync.aligned.m16n8k16.row.col.f32.bf16.bf16.f32 "
        "{%0,%1,%2,%3}, {%4,%5,%6,%7}, {%8,%9}, {%0,%1,%2,%3};"
        : "+f"(c[0]), "+f"(c[1]), "+f"(c[2]), "+f"(c[3])
        : "r"(a[0]), "r"(a[1]), "r"(a[2]), "r"(a[3]), "r"(b[0]), "r"(b[1]));
}
#define CP_ASYNC16(dst, src) \
    asm volatile("cp.async.cg.shared.global [%0], [%1], 16;" :: "r"(dst), "l"(src))
#define CP_COMMIT()  asm volatile("cp.async.commit_group;" ::: "memory")
#define CP_WAIT(n)   asm volatile("cp.async.wait_group %0;" :: "n"(n) : "memory")

__device__ __forceinline__ void split2(float v0, float v1, __nv_bfloat162& hi, __nv_bfloat162& lo) {
    __nv_bfloat16 h0 = __float2bfloat16_rn(v0), h1 = __float2bfloat16_rn(v1);
    __nv_bfloat16 l0 = __float2bfloat16_rn(v0 - __bfloat162float(h0));
    __nv_bfloat16 l1 = __float2bfloat16_rn(v1 - __bfloat162float(h1));
    hi = __nv_bfloat162(h0, h1); lo = __nv_bfloat162(l0, l1);
}

// ---------------- fused conversion kernels ----------------
__global__ void __launch_bounds__(256)
cvt_act(const float4* __restrict__ x, const float4* __restrict__ h, const float4* __restrict__ ssg,
        __nv_bfloat162* __restrict__ xh, __nv_bfloat162* __restrict__ xl,
        __nv_bfloat162* __restrict__ hh, __nv_bfloat162* __restrict__ hl,
        __nv_bfloat162* __restrict__ sgh, __nv_bfloat162* __restrict__ sgl)
{
    int i = blockIdx.x * 256 + threadIdx.x;         // BH/4 chunks
    float4 vx = x[i], vh = h[i], vs = ssg[i];
    __nv_bfloat162 a, b;
    split2(vx.x, vx.y, a, b); xh[2*i] = a;  xl[2*i] = b;
    split2(vx.z, vx.w, a, b); xh[2*i+1] = a; xl[2*i+1] = b;
    split2(vh.x, vh.y, a, b); hh[2*i] = a;  hl[2*i] = b;
    split2(vh.z, vh.w, a, b); hh[2*i+1] = a; hl[2*i+1] = b;
    split2(vs.x + vh.x, vs.y + vh.y, a, b); sgh[2*i] = a;  sgl[2*i] = b;
    split2(vs.z + vh.z, vs.w + vh.w, a, b); sgh[2*i+1] = a; sgl[2*i+1] = b;
}
#define CW1 1310720            // Wx chunks (5120*1024/4)
#define CW2 2621440            // +Ux
#define CW3 3145728            // +a1 (1024*2048/4)
#define CWS 262144             // each H*H/4
__global__ void __launch_bounds__(256)
cvt_w_all(const float4* __restrict__ Wx, const float4* __restrict__ Ux, const float4* __restrict__ a1,
          const float4* __restrict__ sw, const float4* __restrict__ r1,
          const float4* __restrict__ r2, const float4* __restrict__ r3,
          __nv_bfloat162* __restrict__ Wxh, __nv_bfloat162* __restrict__ Wxl,
          __nv_bfloat162* __restrict__ Uxh, __nv_bfloat162* __restrict__ Uxl,
          __nv_bfloat162* __restrict__ a1h, __nv_bfloat162* __restrict__ a1l,
          __nv_bfloat162* __restrict__ swh, __nv_bfloat162* __restrict__ swl,
          __nv_bfloat162* __restrict__ w1h, __nv_bfloat162* __restrict__ w1l,
          __nv_bfloat162* __restrict__ w2h, __nv_bfloat162* __restrict__ w2l,
          __nv_bfloat162* __restrict__ w3h, __nv_bfloat162* __restrict__ w3l)
{
    int i = blockIdx.x * 256 + threadIdx.x;
    const float4* src; __nv_bfloat162 *oh, *ol; int j;
    if      (i < CW1)          { src = Wx; oh = Wxh; ol = Wxl; j = i; }
    else if (i < CW2)          { src = Ux; oh = Uxh; ol = Uxl; j = i - CW1; }
    else if (i < CW3)          { src = a1; oh = a1h; ol = a1l; j = i - CW2; }
    else if (i < CW3 + CWS)    { src = sw; oh = swh; ol = swl; j = i - CW3; }
    else if (i < CW3 + 2*CWS)  { src = r1; oh = w1h; ol = w1l; j = i - CW3 - CWS; }
    else if (i < CW3 + 3*CWS)  { src = r2; oh = w2h; ol = w2l; j = i - CW3 - 2*CWS; }
    else                       { src = r3; oh = w3h; ol = w3l; j = i - CW3 - 3*CWS; }
    float4 v = src[j];
    __nv_bfloat162 a, b;
    split2(v.x, v.y, a, b); oh[2*j] = a;   ol[2*j] = b;
    split2(v.z, v.w, a, b); oh[2*j+1] = a; ol[2*j+1] = b;
}

// ---------------- bf16-split mma.sync GEMM (128x128 CTA, 2-stage, 2 CTAs/SM) ----------------
// C[M,N] = epi( A1@W1^T [+ A2@W2^T] + b1 [+ b2] )
// MODE: 0 fp32 out ; 1 relu fp32 ; 2 gate acts ; 3 r3+cell fused ; 4 relu + bf16 pair out
template<int MODE>
__global__ void __launch_bounds__(256, 2)
mma_gemm(const __nv_bfloat16* __restrict__ A1h, const __nv_bfloat16* __restrict__ A1l, int lda1,
         const __nv_bfloat16* __restrict__ W1h, const __nv_bfloat16* __restrict__ W1l, int ldw1, int s1,
         const __nv_bfloat16* __restrict__ A2h, const __nv_bfloat16* __restrict__ A2l, int lda2,
         const __nv_bfloat16* __restrict__ W2h, const __nv_bfloat16* __restrict__ W2l, int ldw2, int s2,
         const float* __restrict__ b1, const float* __restrict__ b2,
         float* __restrict__ Cf, __nv_bfloat16* __restrict__ Chi, __nv_bfloat16* __restrict__ Clo,
         int ldc,
         const float* __restrict__ gates, const float* __restrict__ c_prev,
         const float* __restrict__ alphav, const float* __restrict__ ssg,
         float* __restrict__ out_h, float* __restrict__ out_c)
{
    extern __shared__ char smem[];
    const uint32_t sbase = smem_u32(smem);
    const int tid = threadIdx.x, wid = tid >> 5, lane = tid & 31;
    const int wm = wid >> 2, wn = wid & 3;        // 2 x 4 warp grid, warp 64x32
    const int m0 = blockIdx.y * 128, n0 = blockIdx.x * 128;
    const int S = s1 + s2;

    float acc[4][4][4];
#pragma unroll
    for (int a = 0; a < 4; ++a)
#pragma unroll
        for (int b = 0; b < 4; ++b)
#pragma unroll
            for (int q = 0; q < 4; ++q) acc[a][b][q] = 0.f;

    auto issue_load = [&](int s) {
        const __nv_bfloat16 *Ah, *Al, *Wh, *Wl; int lda, ldw, koff;
        if (s < s1) { Ah = A1h; Al = A1l; Wh = W1h; Wl = W1l; lda = lda1; ldw = ldw1; koff = s * 32; }
        else        { Ah = A2h; Al = A2l; Wh = W2h; Wl = W2l; lda = lda2; ldw = ldw2; koff = (s - s1) * 32; }
        const __nv_bfloat16* srcs[4] = {Ah, Al, Wh, Wl};
        uint32_t dst0 = sbase + (uint32_t)(s & 1) * STG_BYTES;
#pragma unroll
        for (int arr = 0; arr < 4; ++arr) {
            const __nv_bfloat16* src = srcs[arr];
            int ldx = (arr < 2) ? lda : ldw;
            int rb  = (arr < 2) ? m0  : n0;
#pragma unroll
            for (int i = 0; i < 2; ++i) {
                int idx = tid + i * 256;           // 512 16B chunks per array
                int row = idx >> 2, c = idx & 3;
                const __nv_bfloat16* g = src + (size_t)(rb + row) * ldx + koff + c * 8;
                uint32_t d = dst0 + arr * ARR_BYTES + row * 80 + c * 16;
                CP_ASYNC16(d, g);
            }
        }
        CP_COMMIT();
    };

    issue_load(0);

    for (int s = 0; s < S; ++s) {
        if (s + 1 < S) { issue_load(s + 1); CP_WAIT(1); }
        else           { CP_WAIT(0); }
        __syncthreads();

        uint32_t SB = sbase + (uint32_t)(s & 1) * STG_BYTES;
        uint32_t Ahb = SB, Alb = SB + ARR_BYTES;
        uint32_t Whb = SB + 2 * ARR_BYTES, Wlb = SB + 3 * ARR_BYTES;

#pragma unroll
        for (int k16 = 0; k16 < 2; ++k16) {
            const int k0 = k16 * 16;
            // B fragments: 2 ldsm4 (hi) + 2 ldsm4 (lo) cover 4 n-blocks at this k16
            uint32_t bh[4][2], bl[4][2];
            {
                const int g = lane >> 3;          // 0..3
                const int rb = wn * 32 + ((g >> 1) << 3) + (lane & 7);
                const int cb = k0 + ((g & 1) << 3);
#pragma unroll
                for (int p = 0; p < 2; ++p) {     // pair p covers nb=2p, 2p+1
                    uint32_t off = (uint32_t)((rb + p * 16) * RS + cb) * 2;
                    ldsm4(bh[2*p][0], bh[2*p][1], bh[2*p+1][0], bh[2*p+1][1], Whb + off);
                    ldsm4(bl[2*p][0], bl[2*p][1], bl[2*p+1][0], bl[2*p+1][1], Wlb + off);
                }
            }
            const int ra = wm * 64 + (lane & 15);
            const int ca = k0 + ((lane >> 4) << 3);
#pragma unroll
            for (int mb = 0; mb < 4; ++mb) {
                uint32_t ah[4], al[4];
                uint32_t off = (uint32_t)((ra + mb * 16) * RS + ca) * 2;
                ldsm4(ah[0], ah[1], ah[2], ah[3], Ahb + off);
                ldsm4(al[0], al[1], al[2], al[3], Alb + off);
                // split-major: accumulator RAW distance = 4
#pragma unroll
                for (int nb = 0; nb < 4; ++nb) mma16816(acc[mb][nb], ah, bh[nb]);
#pragma unroll
                for (int nb = 0; nb < 4; ++nb) mma16816(acc[mb][nb], ah, bl[nb]);
#pragma unroll
                for (int nb = 0; nb < 4; ++nb) mma16816(acc[mb][nb], al, bh[nb]);
            }
        }
        __syncthreads();
    }

    // ---------------- epilogue ----------------
#pragma unroll
    for (int mb = 0; mb < 4; ++mb) {
#pragma unroll
        for (int nb = 0; nb < 4; ++nb) {
#pragma unroll
            for (int h = 0; h < 2; ++h) {
                const int m = m0 + wm * 64 + mb * 16 + (lane >> 2) + h * 8;
                const int n = n0 + wn * 32 + nb * 8 + 2 * (lane & 3);
                float v0 = acc[mb][nb][2 * h]     + b1[n];
                float v1 = acc[mb][nb][2 * h + 1] + b1[n + 1];
                if (b2) { v0 += b2[n]; v1 += b2[n + 1]; }
                if (MODE == 1 || MODE == 4) { v0 = fmaxf(v0, 0.f); v1 = fmaxf(v1, 0.f); }
                if (MODE == 2) {
                    const int g = n >> 10;        // both cols same gate (n even)
                    if (g == 3) { v0 = tanhf(v0); v1 = tanhf(v1); }
                    else { v0 = 1.f / (1.f + __expf(-v0)); v1 = 1.f / (1.f + __expf(-v1)); }
                }
                const size_t gm = (size_t)m * ldc + n;
                if (MODE == 4) {
                    __nv_bfloat162 hi2, lo2;
                    split2(v0, v1, hi2, lo2);
                    *(__nv_bfloat162*)(Chi + gm) = hi2;
                    *(__nv_bfloat162*)(Clo + gm) = lo2;
                } else if (MODE == 3) {
                    const size_t gb = (size_t)m * NG + n;
                    const float a = alphav[m];
                    float2 cp = *(const float2*)(c_prev + gm);
                    float2 sg = *(const float2*)(ssg + gm);
                    float c0 = gates[gb + 1024] * cp.x
                             + gates[gb] * gates[gb + 3072] * gates[gb + 4096] * a * sg.x + v0;
                    float c1 = gates[gb + 1025] * cp.y
                             + gates[gb + 1] * gates[gb + 3073] * gates[gb + 4097] * a * sg.y + v1;
                    float2 oc; oc.x = c0; oc.y = c1;
                    float2 oh; oh.x = gates[gb + 2048] * tanhf(c0);
                    oh.y = gates[gb + 2049] * tanhf(c1);
                    *(float2*)(out_c + gm) = oc;
                    *(float2*)(out_h + gm) = oh;
                } else {
                    float2 o; o.x = v0; o.y = v1;
                    *(float2*)(Cf + gm) = o;
                }
            }
        }
    }
}

// ---------------- alpha: sigmoid(ah @ a2_w^T + a2_b) ----------------
__global__ void __launch_bounds__(256)
alpha_kernel(const float* __restrict__ ah, const float* __restrict__ a2w,
             const float* __restrict__ a2b, float* __restrict__ alpha)
{
    const int m = blockIdx.x;
    const int t = threadIdx.x;
    float s = 0.f;
#pragma unroll
    for (int k = t; k < 1024; k += 256)
        s += ah[(size_t)m * 1024 + k] * a2w[k];
    for (int o = 16; o; o >>= 1) s += __shfl_down_sync(0xffffffffu, s, o);
    __shared__ float red[8];
    if ((t & 31) == 0) red[t >> 5] = s;
    __syncthreads();
    if (t == 0) {
        float tot = 0.f;
#pragma unroll
        for (int i = 0; i < 8; ++i) tot += red[i];
        alpha[m] = 1.f / (1.f + __expf(-(tot + a2b[0])));
    }
}

// ---------------- launch ----------------
extern "C" void kernel_launch(void* const* d_in, const int* in_sizes, int n_in,
                              void* d_out, int out_size)
{
    const float* x      = (const float*)d_in[0];
    const float* h_prev = (const float*)d_in[1];
    const float* c_prev = (const float*)d_in[2];
    const float* ssg_st = (const float*)d_in[3];
    const float* Wx     = (const float*)d_in[4];
    const float* bWx    = (const float*)d_in[5];
    const float* Ux     = (const float*)d_in[6];
    const float* bUx    = (const float*)d_in[7];
    const float* a1_w   = (const float*)d_in[8];
    const float* a1_b   = (const float*)d_in[9];
    const float* a2_w   = (const float*)d_in[10];
    const float* a2_b   = (const float*)d_in[11];
    const float* r1_w   = (const float*)d_in[12];
    const float* r1_b   = (const float*)d_in[13];
    const float* r2_w   = (const float*)d_in[14];
    const float* r2_b   = (const float*)d_in[15];
    const float* r3_w   = (const float*)d_in[16];
    const float* r3_b   = (const float*)d_in[17];
    const float* ssg_w  = (const float*)d_in[18];
    const float* ssg_b  = (const float*)d_in[19];

    float* out = (float*)d_out;
    float* out_h   = out;
    float* out_c   = out + (size_t)BH;
    float* out_ssg = out + 2 * (size_t)BH;

    __nv_bfloat16 *xh, *xl, *hh, *hl, *sgh, *sgl, *r1h, *r1l, *r2h, *r2l;
    __nv_bfloat16 *Wxh, *Wxl, *Uxh, *Uxl, *a1h, *a1l, *swh, *swl, *w1h, *w1l, *w2h, *w2l, *w3h, *w3l;
    float *gates, *ah, *alpha;
    cudaGetSymbolAddress((void**)&xh, s_x_hi);   cudaGetSymbolAddress((void**)&xl, s_x_lo);
    cudaGetSymbolAddress((void**)&hh, s_h_hi);   cudaGetSymbolAddress((void**)&hl, s_h_lo);
    cudaGetSymbolAddress((void**)&sgh, s_sg_hi); cudaGetSymbolAddress((void**)&sgl, s_sg_lo);
    cudaGetSymbolAddress((void**)&r1h, s_r1_hi); cudaGetSymbolAddress((void**)&r1l, s_r1_lo);
    cudaGetSymbolAddress((void**)&r2h, s_r2_hi); cudaGetSymbolAddress((void**)&r2l, s_r2_lo);
    cudaGetSymbolAddress((void**)&Wxh, w_Wx_hi); cudaGetSymbolAddress((void**)&Wxl, w_Wx_lo);
    cudaGetSymbolAddress((void**)&Uxh, w_Ux_hi); cudaGetSymbolAddress((void**)&Uxl, w_Ux_lo);
    cudaGetSymbolAddress((void**)&a1h, w_a1_hi); cudaGetSymbolAddress((void**)&a1l, w_a1_lo);
    cudaGetSymbolAddress((void**)&swh, w_sw_hi); cudaGetSymbolAddress((void**)&swl, w_sw_lo);
    cudaGetSymbolAddress((void**)&w1h, w_r1_hi); cudaGetSymbolAddress((void**)&w1l, w_r1_lo);
    cudaGetSymbolAddress((void**)&w2h, w_r2_hi); cudaGetSymbolAddress((void**)&w2l, w_r2_lo);
    cudaGetSymbolAddress((void**)&w3h, w_r3_hi); cudaGetSymbolAddress((void**)&w3l, w_r3_lo);
    cudaGetSymbolAddress((void**)&gates, g_gates);
    cudaGetSymbolAddress((void**)&ah, g_ah);
    cudaGetSymbolAddress((void**)&alpha, g_alpha);

    cudaFuncSetAttribute(mma_gemm<0>, cudaFuncAttributeMaxDynamicSharedMemorySize, SMEM_BYTES);
    cudaFuncSetAttribute(mma_gemm<1>, cudaFuncAttributeMaxDynamicSharedMemorySize, SMEM_BYTES);
    cudaFuncSetAttribute(mma_gemm<2>, cudaFuncAttributeMaxDynamicSharedMemorySize, SMEM_BYTES);
    cudaFuncSetAttribute(mma_gemm<3>, cudaFuncAttributeMaxDynamicSharedMemorySize, SMEM_BYTES);
    cudaFuncSetAttribute(mma_gemm<4>, cudaFuncAttributeMaxDynamicSharedMemorySize, SMEM_BYTES);

    const dim3 blk(256);

    // fused conversions (2 launches)
    cvt_act<<<BH / 4 / 256, blk>>>((const float4*)x, (const float4*)h_prev, (const float4*)ssg_st,
                                   (__nv_bfloat162*)xh, (__nv_bfloat162*)xl,
                                   (__nv_bfloat162*)hh, (__nv_bfloat162*)hl,
                                   (__nv_bfloat162*)sgh, (__nv_bfloat162*)sgl);
    cvt_w_all<<<(CW3 + 4*CWS) / 256, blk>>>((const float4*)Wx, (const float4*)Ux, (const float4*)a1_w,
                                            (const float4*)ssg_w, (const float4*)r1_w,
                                            (const float4*)r2_w, (const float4*)r3_w,
                                            (__nv_bfloat162*)Wxh, (__nv_bfloat162*)Wxl,
                                            (__nv_bfloat162*)Uxh, (__nv_bfloat162*)Uxl,
                                            (__nv_bfloat162*)a1h, (__nv_bfloat162*)a1l,
                                            (__nv_bfloat162*)swh, (__nv_bfloat162*)swl,
                                            (__nv_bfloat162*)w1h, (__nv_bfloat162*)w1l,
                                            (__nv_bfloat162*)w2h, (__nv_bfloat162*)w2l,
                                            (__nv_bfloat162*)w3h, (__nv_bfloat162*)w3l);

    const dim3 grid_g(NG / 128, BB / 128);   // 40 x 32
    const dim3 grid_h(HH / 128, BB / 128);   // 8 x 32

    // gates = act( x@Wx^T + h@Ux^T + biases )
    mma_gemm<2><<<grid_g, blk, SMEM_BYTES>>>(xh, xl, 1024, Wxh, Wxl, 1024, 32,
                                             hh, hl, 1024, Uxh, Uxl, 1024, 32,
                                             bWx, bUx, gates, nullptr, nullptr, NG,
                                             nullptr, nullptr, nullptr, nullptr, nullptr, nullptr);
    // alpha hidden = relu( x@a1[:, :1024]^T + h@a1[:, 1024:]^T + a1_b )
    mma_gemm<1><<<grid_h, blk, SMEM_BYTES>>>(xh, xl, 1024, a1h, a1l, 2048, 32,
                                             hh, hl, 1024, a1h + 1024, a1l + 1024, 2048, 32,
                                             a1_b, nullptr, ah, nullptr, nullptr, HH,
                                             nullptr, nullptr, nullptr, nullptr, nullptr, nullptr);
    alpha_kernel<<<BB, blk>>>(ah, a2_w, a2_b, alpha);
    // ssg_new = (ssg+h)@ssg_w^T + ssg_b
    mma_gemm<0><<<grid_h, blk, SMEM_BYTES>>>(sgh, sgl, 1024, swh, swl, 1024, 32,
                                             nullptr, nullptr, 0, nullptr, nullptr, 0, 0,
                                             ssg_b, nullptr, out_ssg, nullptr, nullptr, HH,
                                             nullptr, nullptr, nullptr, nullptr, nullptr, nullptr);
    // r1 = relu(h@r1_w^T + b) -> bf16 pair
    mma_gemm<4><<<grid_h, blk, SMEM_BYTES>>>(hh, hl, 1024, w1h, w1l, 1024, 32,
                                             nullptr, nullptr, 0, nullptr, nullptr, 0, 0,
                                             r1_b, nullptr, nullptr, r1h, r1l, HH,
                                             nullptr, nullptr, nullptr, nullptr, nullptr, nullptr);
    // r2 = relu(r1@r2_w^T + b) -> bf16 pair
    mma_gemm<4><<<grid_h, blk, SMEM_BYTES>>>(r1h, r1l, 1024, w2h, w2l, 1024, 32,
                                             nullptr, nullptr, 0, nullptr, nullptr, 0, 0,
                                             r2_b, nullptr, nullptr, r2h, r2l, HH,
                                             nullptr, nullptr, nullptr, nullptr, nullptr, nullptr);
    // residual GEMM + fused LSTM cell -> out_h, out_c
    mma_gemm<3><<<grid_h, blk, SMEM_BYTES>>>(r2h, r2l, 1024, w3h, w3l, 1024, 32,
                                             nullptr, nullptr, 0, nullptr, nullptr, 0, 0,
                                             r3_b, nullptr, nullptr, nullptr, nullptr, HH,
                                             gates, c_prev, alpha, out_ssg, out_h, out_c);
}